// round 5
// baseline (speedup 1.0000x reference)
#include <cuda_runtime.h>

#define NN 100000
#define NE 1600000
#define C  128        // IN_CH == HEADS*OUT_CH == 128

// In-degree mask (node appears as a destination `col`)
__device__ int g_mark[NN];

__global__ void k_zero() {
    int i = blockIdx.x * 256 + threadIdx.x;
    if (i < NN) g_mark[i] = 0;
}

__global__ void k_mark(const int* __restrict__ col) {
    int e = blockIdx.x * 256 + threadIdx.x;
    if (e < NE) {
        int n = col[e];
        if (n >= 0 && n < NN) g_mark[n] = 1;   // guard: free if dtype theory holds
    }
}

// Packed dual-fp32 FMA (Blackwell f32x2 pipe: doubles fp32 FMA throughput)
__device__ __forceinline__ float2 ffma2(float2 a, float2 b, float2 c) {
    union F2U { float2 f; unsigned long long u; };
    F2U A, B, Cc, D;
    A.f = a; B.f = b; Cc.f = c;
    asm("fma.rn.f32x2 %0, %1, %2, %3;"
        : "=l"(D.u) : "l"(A.u), "l"(B.u), "l"(Cc.u));
    return D.f;
}

// out[m, n] = mask[m] * sum_k x[m,k] * w[k,n]
// BM=64 rows/block, full N=128, BK=16 chunks of W staged in smem.
// 128 threads, 8x8 thread tile (ty=tid>>4 -> rows 8*ty.., tx=tid&15 -> cols 8*tx..)
__global__ void __launch_bounds__(128) k_gemm(
    const float* __restrict__ x, const float* __restrict__ w,
    float* __restrict__ out)
{
    __shared__ float As[64 * C];   // 32 KB, quad-swizzled rows
    __shared__ float Bs[16 * C];   // 8 KB

    const int tid = threadIdx.x;
    const int m0  = blockIdx.x * 64;

    // ---- Load full A tile (64 x 128), swizzle: quad position ^ (((row>>3)&1)<<2)
    {
        const int q  = tid & 31;    // k-quad 0..31
        const int r0 = tid >> 5;    // 0..3
        #pragma unroll
        for (int i = 0; i < 16; i++) {
            int r  = r0 + 4 * i;
            int gm = m0 + r;
            float4 v = make_float4(0.f, 0.f, 0.f, 0.f);
            if (gm < NN) v = *(const float4*)(x + (size_t)gm * C + 4 * q);
            int sw = ((r >> 3) & 1) << 2;
            *(float4*)(As + r * C + ((4 * q) ^ sw)) = v;
        }
    }

    const int tx  = tid & 15;          // cols 8*tx .. 8*tx+7
    const int ty  = tid >> 4;          // rows 8*ty .. 8*ty+7
    const int asw = (ty & 1) << 2;     // (8*ty+j)>>3 == ty  for j<8

    float2 acc[8][4];
    #pragma unroll
    for (int j = 0; j < 8; j++)
        #pragma unroll
        for (int c = 0; c < 4; c++) acc[j][c] = make_float2(0.f, 0.f);

    for (int k0 = 0; k0 < C; k0 += 16) {
        __syncthreads();
        // ---- stage W[k0..k0+15][:] into Bs (row-major, direct float4 copy)
        {
            const int q  = tid & 31;
            const int kr = tid >> 5;   // 0..3
            #pragma unroll
            for (int i = 0; i < 4; i++) {
                int kk = kr + 4 * i;
                *(float4*)(Bs + kk * C + 4 * q) =
                    *(const float4*)(w + (size_t)(k0 + kk) * C + 4 * q);
            }
        }
        __syncthreads();

        #pragma unroll
        for (int kk = 0; kk < 16; kk += 4) {
            float4 a[8];
            #pragma unroll
            for (int j = 0; j < 8; j++)
                a[j] = *(const float4*)(As + (8 * ty + j) * C + ((k0 + kk) ^ asw));

            #pragma unroll
            for (int dk = 0; dk < 4; dk++) {
                const float* bp = Bs + (kk + dk) * C + 8 * tx;
                float4 b0 = *(const float4*)(bp);
                float4 b1 = *(const float4*)(bp + 4);
                float2 bb[4];
                bb[0] = make_float2(b0.x, b0.y);
                bb[1] = make_float2(b0.z, b0.w);
                bb[2] = make_float2(b1.x, b1.y);
                bb[3] = make_float2(b1.z, b1.w);
                #pragma unroll
                for (int j = 0; j < 8; j++) {
                    float av = (dk == 0) ? a[j].x : (dk == 1) ? a[j].y
                             : (dk == 2) ? a[j].z : a[j].w;
                    float2 av2 = make_float2(av, av);
                    #pragma unroll
                    for (int c = 0; c < 4; c++)
                        acc[j][c] = ffma2(av2, bb[c], acc[j][c]);
                }
            }
        }
    }

    // ---- epilogue: multiply by in-degree mask, store
    #pragma unroll
    for (int j = 0; j < 8; j++) {
        int gm = m0 + 8 * ty + j;
        if (gm < NN) {
            float msk = g_mark[gm] ? 1.0f : 0.0f;
            float4 o0 = make_float4(acc[j][0].x * msk, acc[j][0].y * msk,
                                    acc[j][1].x * msk, acc[j][1].y * msk);
            float4 o1 = make_float4(acc[j][2].x * msk, acc[j][2].y * msk,
                                    acc[j][3].x * msk, acc[j][3].y * msk);
            float* op = out + (size_t)gm * C + 8 * tx;
            *(float4*)(op)     = o0;
            *(float4*)(op + 4) = o1;
        }
    }
}

extern "C" void kernel_launch(void* const* d_in, const int* in_sizes, int n_in,
                              void* d_out, int out_size) {
    // Identify inputs by element count (robust to metadata ordering):
    //   x:          100000*128 = 12,800,000 f32
    //   weight:     128*128    =     16,384 f32
    //   att:        1*4*64     =        256 f32  (mathematically irrelevant:
    //               softmax weights sum to 1 over segments keyed identically
    //               to the message source, so attention collapses to a mask)
    //   edge_index: 2*1600000  =  3,200,000 int32 (JAX x64-disabled downcast)
    const float* x = nullptr;
    const float* w = nullptr;
    const int*   ei = nullptr;
    for (int i = 0; i < n_in; i++) {
        if (in_sizes[i] == NN * C)      x  = (const float*)d_in[i];
        else if (in_sizes[i] == C * C)  w  = (const float*)d_in[i];
        else if (in_sizes[i] == 2 * NE) ei = (const int*)d_in[i];
    }
    const int* col = ei + NE;   // row-major [2, NE]: second row is `col`
    float* out = (float*)d_out;

    k_zero<<<(NN + 255) / 256, 256>>>();
    k_mark<<<(NE + 255) / 256, 256>>>(col);
    k_gemm<<<(NN + 63) / 64, 128>>>(x, w, out);
}

// round 9
// speedup vs baseline: 2.4551x; 2.4551x over previous
#include <cuda_runtime.h>
#include <cuda_bf16.h>
#include <cstdint>

#define NN 100000
#define NE 1600000
#define C  128        // IN_CH == HEADS*OUT_CH == 128
#define MT 64         // rows per CTA
#define NBLK ((NN + MT - 1) / MT)   // 1563

// ---------------- in-degree mask ----------------
__device__ int g_mark[NN];

__global__ void k_zero4() {
    int i = blockIdx.x * 256 + threadIdx.x;
    if (i * 4 < NN) *(int4*)(g_mark + i * 4) = make_int4(0, 0, 0, 0);  // NN % 4 == 0
}

__global__ void k_mark(const int* __restrict__ col) {
    int e = blockIdx.x * 256 + threadIdx.x;
    if (e < NE) {
        int n = col[e];
        if (n >= 0 && n < NN) g_mark[n] = 1;
    }
}

// ---------------- helpers ----------------
__device__ __forceinline__ uint32_t smem_u32(const void* p) {
    uint32_t a;
    asm("{ .reg .u64 t; cvta.to.shared.u64 t, %1; cvt.u32.u64 %0, t; }"
        : "=r"(a) : "l"(p));
    return a;
}

#define LDSM_X4(r, addr) \
    asm volatile("ldmatrix.sync.aligned.m8n8.x4.shared.b16 {%0,%1,%2,%3}, [%4];" \
        : "=r"((r)[0]), "=r"((r)[1]), "=r"((r)[2]), "=r"((r)[3]) : "r"(addr))

__device__ __forceinline__ void mma16816(float* c, const uint32_t* a,
                                         uint32_t b0, uint32_t b1) {
    asm volatile(
        "mma.sync.aligned.m16n8k16.row.col.f32.bf16.bf16.f32 "
        "{%0,%1,%2,%3}, {%4,%5,%6,%7}, {%8,%9}, {%0,%1,%2,%3};"
        : "+f"(c[0]), "+f"(c[1]), "+f"(c[2]), "+f"(c[3])
        : "r"(a[0]), "r"(a[1]), "r"(a[2]), "r"(a[3]), "r"(b0), "r"(b1));
}

union BF2U { __nv_bfloat162 b; uint32_t u; };

__device__ __forceinline__ void split_pack(float4 v, uint2& hi, uint2& lo) {
    __nv_bfloat16 h0 = __float2bfloat16(v.x), h1 = __float2bfloat16(v.y),
                  h2 = __float2bfloat16(v.z), h3 = __float2bfloat16(v.w);
    __nv_bfloat16 l0 = __float2bfloat16(v.x - __bfloat162float(h0));
    __nv_bfloat16 l1 = __float2bfloat16(v.y - __bfloat162float(h1));
    __nv_bfloat16 l2 = __float2bfloat16(v.z - __bfloat162float(h2));
    __nv_bfloat16 l3 = __float2bfloat16(v.w - __bfloat162float(h3));
    BF2U a, b, c, d;
    a.b = __nv_bfloat162(h0, h1); b.b = __nv_bfloat162(h2, h3);
    c.b = __nv_bfloat162(l0, l1); d.b = __nv_bfloat162(l2, l3);
    hi = make_uint2(a.u, b.u);
    lo = make_uint2(c.u, d.u);
}

// SMEM layout (bytes). Tiles stored bf16, row stride 256B, XOR swizzle on
// 16B chunks: byteoff ^ ((row&7)<<4)  (bits 4-6) -> conflict-free ldmatrix.
#define SM_AH 0                  // A hi: 64 x 128 bf16 = 16 KB
#define SM_AL 16384              // A lo
#define SM_BH 32768              // Wt hi: 128 x 128 bf16 = 32 KB
#define SM_BL 65536              // Wt lo
#define SM_TOTAL 98304           // 96 KB -> 2 CTAs / SM

// out[m,n] = mask[m] * sum_k x[m,k] * w[k,n]
// 3-pass split-bf16: Ahi*Bhi + Ahi*Blo + Alo*Bhi  (fp32 accum)
__global__ void __launch_bounds__(256, 2) k_tc(
    const float* __restrict__ x, const float* __restrict__ w,
    float* __restrict__ out)
{
    extern __shared__ char smem[];
    const uint32_t sb = smem_u32(smem);
    const int tid = threadIdx.x;
    const int l   = tid & 31;
    const int wid = tid >> 5;
    const int wm  = wid >> 2;          // 0..1 : rows wm*32 ..
    const int wn  = wid & 3;           // 0..3 : cols wn*32 ..
    const int m0  = blockIdx.x * MT;

    // ---- A tile: coalesced f32 loads (warp = one row), split, swizzled store
    #pragma unroll
    for (int it = 0; it < 8; it++) {
        int i   = tid + 256 * it;
        int row = i >> 5;
        int c4  = i & 31;
        int gm  = m0 + row;
        float4 v = make_float4(0.f, 0.f, 0.f, 0.f);
        if (gm < NN) v = *(const float4*)(x + (size_t)gm * C + 4 * c4);
        uint2 hi, lo;
        split_pack(v, hi, lo);
        uint32_t off = row * 256 + ((c4 * 8) ^ ((row & 7) << 4));
        *(uint2*)(smem + SM_AH + off) = hi;
        *(uint2*)(smem + SM_AL + off) = lo;
    }

    // ---- B tile: Wt[n][k] = w[k][n], coalesced over n at fixed k
    {
        const int n  = tid & 127;
        const int kh = (tid >> 7) * 64;
        #pragma unroll
        for (int k0 = kh; k0 < kh + 64; k0 += 4) {
            float4 v;
            v.x = w[(size_t)(k0 + 0) * C + n];
            v.y = w[(size_t)(k0 + 1) * C + n];
            v.z = w[(size_t)(k0 + 2) * C + n];
            v.w = w[(size_t)(k0 + 3) * C + n];
            uint2 hi, lo;
            split_pack(v, hi, lo);
            uint32_t off = n * 256 + ((k0 * 2) ^ ((n & 7) << 4));
            *(uint2*)(smem + SM_BH + off) = hi;
            *(uint2*)(smem + SM_BL + off) = lo;
        }
    }
    __syncthreads();

    // ---- per-lane ldmatrix address components
    // A x4: matrices (r0..7,k0..7)(r8..15,k0..7)(r0..7,k8..15)(r8..15,k8..15)
    const uint32_t aRow = (l & 7) + ((l >> 3) & 1) * 8;
    const uint32_t aK16 = (l >> 4) * 16;           // +8 k -> +16 bytes
    // B x4: (n0..7,k0..7)(n0..7,k8..15)(n8..15,k0..7)(n8..15,k8..15)
    const uint32_t bN   = (l & 7) + ((l >> 4) & 1) * 8;
    const uint32_t bK16 = ((l >> 3) & 1) * 16;
    const uint32_t swz  = (l & 7) << 4;            // row&7 == l&7 for both
    const uint32_t aOff0 = (wm * 32 + aRow) * 256;
    const uint32_t bOff0 = (wn * 32 + bN) * 256;

    float acc[2][4][4];
    #pragma unroll
    for (int mt = 0; mt < 2; mt++)
        #pragma unroll
        for (int nt = 0; nt < 4; nt++)
            #pragma unroll
            for (int i = 0; i < 4; i++) acc[mt][nt][i] = 0.f;

    #pragma unroll
    for (int ks = 0; ks < 8; ks++) {
        const uint32_t kbA = ((uint32_t)(ks * 32) + aK16) ^ swz;
        const uint32_t kbB = ((uint32_t)(ks * 32) + bK16) ^ swz;

        uint32_t ah[2][4], al[2][4], bh[2][4], bl[2][4];
        #pragma unroll
        for (int mt = 0; mt < 2; mt++) {
            uint32_t adr = sb + SM_AH + aOff0 + mt * 4096 + kbA;
            LDSM_X4(ah[mt], adr);
            LDSM_X4(al[mt], adr + (SM_AL - SM_AH));
        }
        #pragma unroll
        for (int np = 0; np < 2; np++) {
            uint32_t adr = sb + SM_BH + bOff0 + np * 4096 + kbB;
            LDSM_X4(bh[np], adr);
            LDSM_X4(bl[np], adr + (SM_BL - SM_BH));
        }

        #pragma unroll
        for (int mt = 0; mt < 2; mt++)
            #pragma unroll
            for (int nt = 0; nt < 4; nt++) {
                uint32_t bh0 = bh[nt >> 1][(nt & 1) * 2];
                uint32_t bh1 = bh[nt >> 1][(nt & 1) * 2 + 1];
                uint32_t bl0 = bl[nt >> 1][(nt & 1) * 2];
                uint32_t bl1 = bl[nt >> 1][(nt & 1) * 2 + 1];
                mma16816(acc[mt][nt], ah[mt], bh0, bh1);   // hi*hi
                mma16816(acc[mt][nt], ah[mt], bl0, bl1);   // hi*lo
                mma16816(acc[mt][nt], al[mt], bh0, bh1);   // lo*hi
            }
    }

    // ---- epilogue: mask + store
    // c frag: c0,c1 -> row = groupID, cols 2*(l&3)+{0,1}; c2,c3 -> row+8
    #pragma unroll
    for (int mt = 0; mt < 2; mt++) {
        int r0 = m0 + wm * 32 + mt * 16 + (l >> 2);
        int r1 = r0 + 8;
        float mk0 = (r0 < NN && g_mark[r0]) ? 1.f : 0.f;
        float mk1 = (r1 < NN && g_mark[r1]) ? 1.f : 0.f;
        #pragma unroll
        for (int nt = 0; nt < 4; nt++) {
            int colc = wn * 32 + nt * 8 + (l & 3) * 2;
            if (r0 < NN)
                *(float2*)(out + (size_t)r0 * C + colc) =
                    make_float2(acc[mt][nt][0] * mk0, acc[mt][nt][1] * mk0);
            if (r1 < NN)
                *(float2*)(out + (size_t)r1 * C + colc) =
                    make_float2(acc[mt][nt][2] * mk1, acc[mt][nt][3] * mk1);
        }
    }
}

extern "C" void kernel_launch(void* const* d_in, const int* in_sizes, int n_in,
                              void* d_out, int out_size) {
    // Identify inputs by element count (robust to metadata ordering):
    //   x: 12,800,000 f32 | weight: 16,384 f32 | att: 256 f32 (irrelevant —
    //   softmax weights sum to 1 over segments keyed identically to the
    //   message source, so attention collapses to an in-degree mask)
    //   edge_index: 3,200,000 int32
    const float* x = nullptr;
    const float* w = nullptr;
    const int*   ei = nullptr;
    for (int i = 0; i < n_in; i++) {
        if (in_sizes[i] == NN * C)      x  = (const float*)d_in[i];
        else if (in_sizes[i] == C * C)  w  = (const float*)d_in[i];
        else if (in_sizes[i] == 2 * NE) ei = (const int*)d_in[i];
    }
    const int* col = ei + NE;
    float* out = (float*)d_out;

    cudaFuncSetAttribute(k_tc, cudaFuncAttributeMaxDynamicSharedMemorySize,
                         SM_TOTAL);

    k_zero4<<<(NN / 4 + 255) / 256, 256>>>();
    k_mark<<<(NE + 255) / 256, 256>>>(col);
    k_tc<<<NBLK, 256, SM_TOTAL>>>(x, w, out);
}

// round 12
// speedup vs baseline: 2.6231x; 1.0684x over previous
#include <cuda_runtime.h>
#include <cuda_bf16.h>
#include <cstdint>

#define NN 100000
#define NE 1600000
#define C  128        // IN_CH == HEADS*OUT_CH == 128
#define MT 64         // rows per CTA
#define NBLK ((NN + MT - 1) / MT)   // 1563

// ---------------- device globals ----------------
__device__ int g_mark[NN];
// Pre-split, pre-transposed, pre-swizzled W tile: hi at [0,32K), lo at [32K,64K)
__device__ __align__(16) char g_wt[65536];

__global__ void k_zero4() {
    int i = blockIdx.x * 256 + threadIdx.x;
    if (i * 4 < NN) *(int4*)(g_mark + i * 4) = make_int4(0, 0, 0, 0);  // NN%4==0
}

__global__ void k_mark(const int* __restrict__ col) {
    int e = blockIdx.x * 256 + threadIdx.x;
    if (e < NE) {
        int n = col[e];
        if (n >= 0 && n < NN) g_mark[n] = 1;
    }
}

// Zero rows with zero in-degree (rare: expected ~0 rows). Joins mark + gemm.
__global__ void k_apply(float* __restrict__ out) {
    int n = blockIdx.x * 256 + threadIdx.x;
    if (n < NN && !g_mark[n]) {
        float4 z = make_float4(0.f, 0.f, 0.f, 0.f);
        float4* p = (float4*)(out + (size_t)n * C);
        #pragma unroll
        for (int i = 0; i < 32; i++) p[i] = z;
    }
}

// ---------------- helpers ----------------
__device__ __forceinline__ uint32_t smem_u32(const void* p) {
    uint32_t a;
    asm("{ .reg .u64 t; cvta.to.shared.u64 t, %1; cvt.u32.u64 %0, t; }"
        : "=r"(a) : "l"(p));
    return a;
}

__device__ __forceinline__ void cp16(uint32_t dst, const void* src) {
    asm volatile("cp.async.cg.shared.global [%0], [%1], 16;"
                 :: "r"(dst), "l"(__cvta_generic_to_global(src)) : "memory");
}

#define LDSM_X4(r, addr) \
    asm volatile("ldmatrix.sync.aligned.m8n8.x4.shared.b16 {%0,%1,%2,%3}, [%4];" \
        : "=r"((r)[0]), "=r"((r)[1]), "=r"((r)[2]), "=r"((r)[3]) : "r"(addr))

__device__ __forceinline__ void mma16816(float* c, const uint32_t* a,
                                         uint32_t b0, uint32_t b1) {
    asm volatile(
        "mma.sync.aligned.m16n8k16.row.col.f32.bf16.bf16.f32 "
        "{%0,%1,%2,%3}, {%4,%5,%6,%7}, {%8,%9}, {%0,%1,%2,%3};"
        : "+f"(c[0]), "+f"(c[1]), "+f"(c[2]), "+f"(c[3])
        : "r"(a[0]), "r"(a[1]), "r"(a[2]), "r"(a[3]), "r"(b0), "r"(b1));
}

union BF2U { __nv_bfloat162 b; uint32_t u; };

__device__ __forceinline__ void split_pack2(float4 v, uint2& hi, uint2& lo) {
    __nv_bfloat16 h0 = __float2bfloat16(v.x), h1 = __float2bfloat16(v.y),
                  h2 = __float2bfloat16(v.z), h3 = __float2bfloat16(v.w);
    __nv_bfloat16 l0 = __float2bfloat16(v.x - __bfloat162float(h0));
    __nv_bfloat16 l1 = __float2bfloat16(v.y - __bfloat162float(h1));
    __nv_bfloat16 l2 = __float2bfloat16(v.z - __bfloat162float(h2));
    __nv_bfloat16 l3 = __float2bfloat16(v.w - __bfloat162float(h3));
    BF2U a, b, c, d;
    a.b = __nv_bfloat162(h0, h1); b.b = __nv_bfloat162(h2, h3);
    c.b = __nv_bfloat162(l0, l1); d.b = __nv_bfloat162(l2, l3);
    hi = make_uint2(a.u, b.u);
    lo = make_uint2(c.u, d.u);
}

// Pre-split W: Wt[n][k] = w[k][n], bf16 hi/lo, swizzled exactly like the smem
// layout (row stride 256B, 16B-chunk XOR swizzle). 16 blocks x 256 threads.
__global__ void k_prep(const float* __restrict__ w) {
    int idx = blockIdx.x * 256 + threadIdx.x;   // 0..4095
    int n  = idx & 127;
    int k0 = (idx >> 7) * 4;
    float4 v;
    v.x = w[(size_t)(k0 + 0) * C + n];
    v.y = w[(size_t)(k0 + 1) * C + n];
    v.z = w[(size_t)(k0 + 2) * C + n];
    v.w = w[(size_t)(k0 + 3) * C + n];
    uint2 hi, lo;
    split_pack2(v, hi, lo);
    uint32_t off = n * 256 + ((k0 * 2) ^ ((n & 7) << 4));
    *(uint2*)(g_wt + off)         = hi;
    *(uint2*)(g_wt + 32768 + off) = lo;
}

// SMEM layout (bytes). Row stride 256B, XOR swizzle byteoff ^ ((row&7)<<4).
#define SM_AH 0                  // A hi: 64 x 128 bf16 = 16 KB
#define SM_AL 16384              // A lo
#define SM_BH 32768              // Wt hi+lo contiguous 64 KB (mirrors g_wt)
#define SM_BL 65536
#define SM_TOTAL 98304           // 96 KB -> 2 CTAs / SM

// out[m,n] = sum_k x[m,k]*w[k,n]  (UNMASKED; k_apply zeroes deg-0 rows)
// 3-pass split-bf16: Ahi*Bhi + Ahi*Blo + Alo*Bhi (fp32 accum)
__global__ void __launch_bounds__(256, 2) k_tc(
    const float* __restrict__ x, float* __restrict__ out)
{
    extern __shared__ char smem[];
    const uint32_t sb = smem_u32(smem);
    const int tid = threadIdx.x;
    const int l   = tid & 31;
    const int wid = tid >> 5;
    const int wm  = wid >> 2;          // 0..1 : rows wm*32 ..
    const int wn  = wid & 3;           // 0..3 : cols wn*32 ..
    const int m0  = blockIdx.x * MT;

    // ---- B tile: flat async copy of pre-split/pre-swizzled Wt (64 KB)
    #pragma unroll
    for (int i = 0; i < 16; i++) {
        int c16 = tid + 256 * i;                  // 16B chunk index, 0..4095
        cp16(sb + SM_BH + c16 * 16, g_wt + c16 * 16);
    }
    asm volatile("cp.async.commit_group;" ::: "memory");

    // ---- A tile: coalesced f32 loads, split to bf16 hi/lo, swizzled store
    #pragma unroll
    for (int it = 0; it < 8; it++) {
        int i   = tid + 256 * it;
        int row = i >> 5;
        int c4  = i & 31;
        int gm  = m0 + row;
        float4 v = make_float4(0.f, 0.f, 0.f, 0.f);
        if (gm < NN) v = *(const float4*)(x + (size_t)gm * C + 4 * c4);
        uint2 hi, lo;
        split_pack2(v, hi, lo);
        uint32_t off = row * 256 + ((c4 * 8) ^ ((row & 7) << 4));
        *(uint2*)(smem + SM_AH + off) = hi;
        *(uint2*)(smem + SM_AL + off) = lo;
    }

    asm volatile("cp.async.wait_group 0;" ::: "memory");
    __syncthreads();

    // ---- per-lane ldmatrix address components
    const uint32_t aRow = (l & 7) + ((l >> 3) & 1) * 8;
    const uint32_t aK16 = (l >> 4) * 16;
    const uint32_t bN   = (l & 7) + ((l >> 4) & 1) * 8;
    const uint32_t bK16 = ((l >> 3) & 1) * 16;
    const uint32_t swz  = (l & 7) << 4;
    const uint32_t aOff0 = (wm * 32 + aRow) * 256;
    const uint32_t bOff0 = (wn * 32 + bN) * 256;

    float acc[2][4][4];
    #pragma unroll
    for (int mt = 0; mt < 2; mt++)
        #pragma unroll
        for (int nt = 0; nt < 4; nt++)
            #pragma unroll
            for (int i = 0; i < 4; i++) acc[mt][nt][i] = 0.f;

    #pragma unroll
    for (int ks = 0; ks < 8; ks++) {
        const uint32_t kbA = ((uint32_t)(ks * 32) + aK16) ^ swz;
        const uint32_t kbB = ((uint32_t)(ks * 32) + bK16) ^ swz;

        uint32_t ah[2][4], al[2][4], bh[2][4], bl[2][4];
        #pragma unroll
        for (int mt = 0; mt < 2; mt++) {
            uint32_t adr = sb + SM_AH + aOff0 + mt * 4096 + kbA;
            LDSM_X4(ah[mt], adr);
            LDSM_X4(al[mt], adr + (SM_AL - SM_AH));
        }
        #pragma unroll
        for (int np = 0; np < 2; np++) {
            uint32_t adr = sb + SM_BH + bOff0 + np * 4096 + kbB;
            LDSM_X4(bh[np], adr);
            LDSM_X4(bl[np], adr + (SM_BL - SM_BH));
        }

        #pragma unroll
        for (int mt = 0; mt < 2; mt++)
            #pragma unroll
            for (int nt = 0; nt < 4; nt++) {
                uint32_t bh0 = bh[nt >> 1][(nt & 1) * 2];
                uint32_t bh1 = bh[nt >> 1][(nt & 1) * 2 + 1];
                uint32_t bl0 = bl[nt >> 1][(nt & 1) * 2];
                uint32_t bl1 = bl[nt >> 1][(nt & 1) * 2 + 1];
                mma16816(acc[mt][nt], ah[mt], bh0, bh1);   // hi*hi
                mma16816(acc[mt][nt], ah[mt], bl0, bl1);   // hi*lo
                mma16816(acc[mt][nt], al[mt], bh0, bh1);   // lo*hi
            }
    }

    // ---- epilogue: store (no mask here; k_apply handles deg-0 rows)
    #pragma unroll
    for (int mt = 0; mt < 2; mt++) {
        int r0 = m0 + wm * 32 + mt * 16 + (l >> 2);
        int r1 = r0 + 8;
        #pragma unroll
        for (int nt = 0; nt < 4; nt++) {
            int colc = wn * 32 + nt * 8 + (l & 3) * 2;
            if (r0 < NN)
                *(float2*)(out + (size_t)r0 * C + colc) =
                    make_float2(acc[mt][nt][0], acc[mt][nt][1]);
            if (r1 < NN)
                *(float2*)(out + (size_t)r1 * C + colc) =
                    make_float2(acc[mt][nt][2], acc[mt][nt][3]);
        }
    }
}

extern "C" void kernel_launch(void* const* d_in, const int* in_sizes, int n_in,
                              void* d_out, int out_size) {
    // Identify inputs by element count (robust to metadata ordering):
    //   x: 12,800,000 f32 | weight: 16,384 f32 | att: 256 f32 (irrelevant —
    //   softmax weights sum to 1 over segments keyed identically to the
    //   message source, so attention collapses to an in-degree mask)
    //   edge_index: 3,200,000 int32
    const float* x = nullptr;
    const float* w = nullptr;
    const int*   ei = nullptr;
    for (int i = 0; i < n_in; i++) {
        if (in_sizes[i] == NN * C)      x  = (const float*)d_in[i];
        else if (in_sizes[i] == C * C)  w  = (const float*)d_in[i];
        else if (in_sizes[i] == 2 * NE) ei = (const int*)d_in[i];
    }
    const int* col = ei + NE;
    float* out = (float*)d_out;

    // One-time resources (no device memory allocation involved)
    static cudaStream_t s2;
    static cudaEvent_t ev_fork, ev_mark;
    static bool init = false;
    if (!init) {
        cudaFuncSetAttribute(k_tc, cudaFuncAttributeMaxDynamicSharedMemorySize,
                             SM_TOTAL);
        cudaStreamCreateWithFlags(&s2, cudaStreamNonBlocking);
        cudaEventCreateWithFlags(&ev_fork, cudaEventDisableTiming);
        cudaEventCreateWithFlags(&ev_mark, cudaEventDisableTiming);
        init = true;
    }

    // Fork: mark chain on s2, prep+GEMM on the main (capture) stream.
    cudaEventRecord(ev_fork, 0);
    cudaStreamWaitEvent(s2, ev_fork, 0);
    k_zero4<<<(NN / 4 + 255) / 256, 256, 0, s2>>>();
    k_mark<<<(NE + 255) / 256, 256, 0, s2>>>(col);
    cudaEventRecord(ev_mark, s2);

    k_prep<<<16, 256>>>(w);
    k_tc<<<NBLK, 256, SM_TOTAL>>>(x, out);

    // Join: apply in-degree mask after both the GEMM and the mark chain.
    cudaStreamWaitEvent(0, ev_mark, 0);
    k_apply<<<(NN + 255) / 256, 256>>>(out);
}